// round 6
// baseline (speedup 1.0000x reference)
#include <cuda_runtime.h>

#define HH 224
#define WW 224
#define BB 4
#define SS 21
#define RR 5
#define HW (HH*WW)

// Stage-1 intermediate: 84 shifted images, HWC pixels padded to float4.
// 84 * 50176 * 16B = 67.4 MB (static device scratch — allowed).
__device__ float4 g_x1[SS * BB * HW];

// cos/sin of ANGLES = {-0.5236, -0.2618, 0, 0.2618, 0.5236} (float64-accurate)
__constant__ float c_cos[RR] = {0.86602479158f, 0.96592566784f, 1.0f,
                                0.96592566784f, 0.86602479158f};
__constant__ float c_sin[RR] = {-0.50000106036f, -0.25881963644f, 0.0f,
                                 0.25881963644f,  0.50000106036f};

// ---------------------------------------------------------------------------
// Stage 1: axis-aligned half-pixel shifts with bilinear + zero padding.
// grid: (ceil(HW/256), S*B), block 256. One thread = one pixel of one image.
// ---------------------------------------------------------------------------
__global__ void __launch_bounds__(256) stage1_shift(const float* __restrict__ xs)
{
    int idx = blockIdx.x * 256 + threadIdx.x;
    if (idx >= HW) return;
    int n = blockIdx.y;          // 0..83 = s*B + b
    int s = n >> 2;
    int b = n & 3;
    int h = idx / WW;
    int w = idx - h * WW;

    // Shift table (order: up p=1..5, down p=1..5, left p=1..5, right p=1..5,0).
    // Normalized shift p/(W-1) == p/2 pixels.
    float dx = 0.f, dy = 0.f;
    if      (s < 5)  dy =  (float)(s + 1)  * 0.5f;
    else if (s < 10) dy = -(float)(s - 4)  * 0.5f;
    else if (s < 15) dx =  (float)(s - 9)  * 0.5f;
    else if (s < 20) dx = -(float)(s - 14) * 0.5f;
    // s == 20: identity

    float sx = (float)w + dx;
    float sy = (float)h + dy;
    float x0f = floorf(sx), y0f = floorf(sy);
    int   x0  = (int)x0f,   y0  = (int)y0f;
    float fx = sx - x0f, fy = sy - y0f;

    const float* img = xs + b * (HW * 3);
    float ax = 0.f, ay = 0.f, az = 0.f;
    #pragma unroll
    for (int j = 0; j < 2; j++) {
        int y = y0 + j;
        if ((unsigned)y >= HH) continue;
        float wy = j ? fy : (1.f - fy);
        #pragma unroll
        for (int i = 0; i < 2; i++) {
            int x = x0 + i;
            if ((unsigned)x >= WW) continue;
            float wgt = wy * (i ? fx : (1.f - fx));
            const float* p = img + (y * WW + x) * 3;
            ax += wgt * p[0];
            ay += wgt * p[1];
            az += wgt * p[2];
        }
    }
    g_x1[n * HW + idx] = make_float4(ax, ay, az, 0.f);
}

// ---------------------------------------------------------------------------
// Stage 2: rotation sampling of the shifted batch.
// grid: (ceil(HW/256), R*S*B), block 256. blockIdx.y = output image index m:
//   m = (r*S + s)*B + b  ->  r = m/84, x1 image n = m%84.
// ---------------------------------------------------------------------------
__global__ void __launch_bounds__(256) stage2_rotate(float* __restrict__ out)
{
    int idx = blockIdx.x * 256 + threadIdx.x;
    if (idx >= HW) return;
    int m = blockIdx.y;                 // 0..419
    int r = m / (SS * BB);
    int n = m - r * (SS * BB);          // x1 image index

    int h = idx / WW;
    int w = idx - h * WW;

    const float cx = 0.5f * (WW - 1);   // 111.5 (H == W)
    float u = (float)w - cx;
    float v = (float)h - cx;
    float cs = c_cos[r], sn = c_sin[r];
    float ix =  u * cs + v * sn + cx;
    float iy = -u * sn + v * cs + cx;

    float x0f = floorf(ix), y0f = floorf(iy);
    int   x0  = (int)x0f,   y0  = (int)y0f;
    float fx = ix - x0f, fy = iy - y0f;

    const float4* img = g_x1 + n * HW;
    float ax = 0.f, ay = 0.f, az = 0.f;
    #pragma unroll
    for (int j = 0; j < 2; j++) {
        int y = y0 + j;
        if ((unsigned)y >= HH) continue;
        float wy = j ? fy : (1.f - fy);
        #pragma unroll
        for (int i = 0; i < 2; i++) {
            int x = x0 + i;
            if ((unsigned)x >= WW) continue;
            float wgt = wy * (i ? fx : (1.f - fx));
            float4 pv = __ldg(img + y * WW + x);
            ax += wgt * pv.x;
            ay += wgt * pv.y;
            az += wgt * pv.z;
        }
    }

    int o = (m * HW + idx) * 3;
    out[o + 0] = ax;
    out[o + 1] = ay;
    out[o + 2] = az;
}

extern "C" void kernel_launch(void* const* d_in, const int* in_sizes, int n_in,
                              void* d_out, int out_size)
{
    (void)in_sizes; (void)n_in; (void)out_size;
    const float* xs = (const float*)d_in[0];
    float* out = (float*)d_out;

    dim3 blk(256);
    dim3 g1((HW + 255) / 256, SS * BB);        // (196, 84)
    dim3 g2((HW + 255) / 256, RR * SS * BB);   // (196, 420)

    stage1_shift<<<g1, blk>>>(xs);
    stage2_rotate<<<g2, blk>>>(out);
}

// round 7
// speedup vs baseline: 1.0912x; 1.0912x over previous
#include <cuda_runtime.h>
#include <cuda_fp16.h>

#define HH 224
#define WW 224
#define BB 4
#define SS 21
#define RR 5
#define HW (HH*WW)

// Stage-1 intermediate: 84 shifted images, HWC pixels packed as half4 (8 B).
// 84 * 50176 * 8B = 33.7 MB static device scratch (fits in 126 MB L2).
struct h4 { __half2 ab; __half2 c_; };
__device__ h4 g_x1[SS * BB * HW];

// cos/sin of ANGLES = {-0.5236, -0.2618, 0, 0.2618, 0.5236} (float64-accurate)
__constant__ float c_cos[RR] = {0.86602479158f, 0.96592566784f, 1.0f,
                                0.96592566784f, 0.86602479158f};
__constant__ float c_sin[RR] = {-0.50000106036f, -0.25881963644f, 0.0f,
                                 0.25881963644f,  0.50000106036f};

// ---------------------------------------------------------------------------
// Stage 1: axis-aligned half-pixel shifts, bilinear + zero padding.
// One thread = one pixel of one shifted image. Writes 8B half4.
// ---------------------------------------------------------------------------
__global__ void __launch_bounds__(256) stage1_shift(const float* __restrict__ xs)
{
    int idx = blockIdx.x * 256 + threadIdx.x;
    if (idx >= HW) return;
    int n = blockIdx.y;          // 0..83 = s*B + b
    int s = n >> 2;
    int b = n & 3;
    int h = idx / WW;
    int w = idx - h * WW;

    // Shift order: up p=1..5, down p=1..5, left p=1..5, right p=1..5,0.
    // Normalized shift p/(W-1) maps to p/2 pixels.
    float dx = 0.f, dy = 0.f;
    if      (s < 5)  dy =  (float)(s + 1)  * 0.5f;
    else if (s < 10) dy = -(float)(s - 4)  * 0.5f;
    else if (s < 15) dx =  (float)(s - 9)  * 0.5f;
    else if (s < 20) dx = -(float)(s - 14) * 0.5f;
    // s == 20: identity

    float sx = (float)w + dx;
    float sy = (float)h + dy;
    float x0f = floorf(sx), y0f = floorf(sy);
    int   x0  = (int)x0f,   y0  = (int)y0f;
    float fx = sx - x0f, fy = sy - y0f;

    const float* img = xs + b * (HW * 3);
    float ax = 0.f, ay = 0.f, az = 0.f;
    #pragma unroll
    for (int j = 0; j < 2; j++) {
        int y = y0 + j;
        if ((unsigned)y >= HH) continue;
        float wy = j ? fy : (1.f - fy);
        #pragma unroll
        for (int i = 0; i < 2; i++) {
            int x = x0 + i;
            if ((unsigned)x >= WW) continue;
            float wgt = wy * (i ? fx : (1.f - fx));
            const float* p = img + (y * WW + x) * 3;
            ax += wgt * p[0];
            ay += wgt * p[1];
            az += wgt * p[2];
        }
    }
    h4 v;
    v.ab = __floats2half2_rn(ax, ay);
    v.c_ = __floats2half2_rn(az, 0.f);
    g_x1[n * HW + idx] = v;
}

// ---------------------------------------------------------------------------
// Stage 2: rotation sampling. One thread = 4 consecutive output pixels
// (same row; 224 % 4 == 0). 16 independent LDG.64 gathers per thread,
// 3 STG.128 stores. Branchless zero-padding via weight masking.
// ---------------------------------------------------------------------------
__global__ void __launch_bounds__(256) stage2_rotate(float* __restrict__ out)
{
    int t = blockIdx.x * 256 + threadIdx.x;   // pixel-quad id within image
    if (t >= HW / 4) return;
    int m = blockIdx.y;                       // 0..419
    int r = m / (SS * BB);
    int n = m - r * (SS * BB);

    int idx = t * 4;
    int h = idx / WW;
    int w = idx - h * WW;

    const float cx = 111.5f;                  // 0.5*(W-1), H == W
    float cs = c_cos[r], sn = c_sin[r];
    float u = (float)w - cx;
    float v = (float)h - cx;
    float ix0 =  u * cs + v * sn + cx;        // d(ix)/dw = cs
    float iy0 = -u * sn + v * cs + cx;        // d(iy)/dw = -sn

    const h4* __restrict__ img = g_x1 + n * HW;

    float res[12];
    #pragma unroll
    for (int p = 0; p < 4; p++) {
        float jx = ix0 + (float)p * cs;
        float jy = iy0 - (float)p * sn;
        float x0f = floorf(jx), y0f = floorf(jy);
        int   x0  = (int)x0f,   y0  = (int)y0f;
        float fx = jx - x0f, fy = jy - y0f;

        float wx0 = (1.f - fx) * (((unsigned)x0      < WW) ? 1.f : 0.f);
        float wx1 =         fx * (((unsigned)(x0+1)  < WW) ? 1.f : 0.f);
        float wy0 = (1.f - fy) * (((unsigned)y0      < HH) ? 1.f : 0.f);
        float wy1 =         fy * (((unsigned)(y0+1)  < HH) ? 1.f : 0.f);

        int xc0 = min(max(x0,     0), WW - 1);
        int xc1 = min(max(x0 + 1, 0), WW - 1);
        int yc0 = min(max(y0,     0), HH - 1) * WW;
        int yc1 = min(max(y0 + 1, 0), HH - 1) * WW;

        // 4 independent 8B gathers
        uint2 r00 = __ldg((const uint2*)(img + yc0 + xc0));
        uint2 r01 = __ldg((const uint2*)(img + yc0 + xc1));
        uint2 r10 = __ldg((const uint2*)(img + yc1 + xc0));
        uint2 r11 = __ldg((const uint2*)(img + yc1 + xc1));

        float w00 = wy0 * wx0, w01 = wy0 * wx1;
        float w10 = wy1 * wx0, w11 = wy1 * wx1;

        float2 a00 = __half22float2(*(__half2*)&r00.x);
        float2 b00 = __half22float2(*(__half2*)&r00.y);
        float2 a01 = __half22float2(*(__half2*)&r01.x);
        float2 b01 = __half22float2(*(__half2*)&r01.y);
        float2 a10 = __half22float2(*(__half2*)&r10.x);
        float2 b10 = __half22float2(*(__half2*)&r10.y);
        float2 a11 = __half22float2(*(__half2*)&r11.x);
        float2 b11 = __half22float2(*(__half2*)&r11.y);

        res[p*3 + 0] = w00*a00.x + w01*a01.x + w10*a10.x + w11*a11.x;
        res[p*3 + 1] = w00*a00.y + w01*a01.y + w10*a10.y + w11*a11.y;
        res[p*3 + 2] = w00*b00.x + w01*b01.x + w10*b10.x + w11*b11.x;
    }

    // 12 consecutive floats, 16B-aligned: (m*HW + idx)*3 with idx % 4 == 0.
    float4* o = (float4*)(out + (size_t)m * (HW * 3) + (size_t)idx * 3);
    o[0] = make_float4(res[0], res[1], res[2],  res[3]);
    o[1] = make_float4(res[4], res[5], res[6],  res[7]);
    o[2] = make_float4(res[8], res[9], res[10], res[11]);
}

extern "C" void kernel_launch(void* const* d_in, const int* in_sizes, int n_in,
                              void* d_out, int out_size)
{
    (void)in_sizes; (void)n_in; (void)out_size;
    const float* xs = (const float*)d_in[0];
    float* out = (float*)d_out;

    dim3 blk(256);
    dim3 g1((HW + 255) / 256, SS * BB);            // (196, 84)
    dim3 g2((HW / 4 + 255) / 256, RR * SS * BB);   // (49, 420)

    stage1_shift<<<g1, blk>>>(xs);
    stage2_rotate<<<g2, blk>>>(out);
}

// round 8
// speedup vs baseline: 1.3682x; 1.2538x over previous
#include <cuda_runtime.h>
#include <cuda_fp16.h>

#define HH 224
#define WW 224
#define BB 4
#define SS 21
#define RR 5
#define HW (HH*WW)

#define TILE 32
#define TPB 256
#define IN_DIM 48
#define PITCH 49          // 48 + 1 pad: row step == 1 mod 16 banks-of-8B

// Stage-1 intermediate: 84 shifted images, HWC pixels packed as half4 (8 B).
__device__ uint2 g_x1[SS * BB * HW];    // 33.7 MB

// cos/sin of ANGLES = {-0.5236, -0.2618, 0, 0.2618, 0.5236} (float64-accurate)
__constant__ float c_cos[RR] = {0.86602479158f, 0.96592566784f, 1.0f,
                                0.96592566784f, 0.86602479158f};
__constant__ float c_sin[RR] = {-0.50000106036f, -0.25881963644f, 0.0f,
                                 0.25881963644f,  0.50000106036f};

// ---------------------------------------------------------------------------
// Stage 1: axis-aligned shifts are exactly 2-tap (frac is 0 or 0.5, one axis).
// One thread = one pixel. Writes 8B half4.
// ---------------------------------------------------------------------------
__global__ void __launch_bounds__(256) stage1_shift(const float* __restrict__ xs)
{
    int idx = blockIdx.x * 256 + threadIdx.x;
    if (idx >= HW) return;
    int n = blockIdx.y;          // 0..83 = s*B + b
    int s = n >> 2;
    int b = n & 3;
    int h = idx / WW;
    int w = idx - h * WW;

    // Shift order: up p=1..5 (+y), down p=1..5 (-y), left (+x), right (-x),
    // plus identity. Normalized p/(W-1) -> p/2 pixels.
    int axis;                    // 0 = shift along y, 1 = along x
    float delta;
    if      (s < 5)  { axis = 0; delta =  (float)(s + 1)  * 0.5f; }
    else if (s < 10) { axis = 0; delta = -(float)(s - 4)  * 0.5f; }
    else if (s < 15) { axis = 1; delta =  (float)(s - 9)  * 0.5f; }
    else if (s < 20) { axis = 1; delta = -(float)(s - 14) * 0.5f; }
    else             { axis = 0; delta = 0.f; }

    float coord = (axis == 0 ? (float)h : (float)w) + delta;
    float i0f = floorf(coord);
    int   i0  = (int)i0f;
    float f   = coord - i0f;     // 0 or 0.5

    const float* img = xs + b * (HW * 3);
    float ax = 0.f, ay = 0.f, az = 0.f;
    #pragma unroll
    for (int j = 0; j < 2; j++) {
        int i = i0 + j;
        float wt = j ? f : (1.f - f);
        int y = axis == 0 ? i : h;
        int x = axis == 0 ? w : i;
        if (wt != 0.f && (unsigned)y < HH && (unsigned)x < WW) {
            const float* p = img + (y * WW + x) * 3;
            ax += wt * p[0];
            ay += wt * p[1];
            az += wt * p[2];
        }
    }
    __half2 lo = __floats2half2_rn(ax, ay);
    __half2 hi = __floats2half2_rn(az, 0.f);
    uint2 v;
    v.x = *(unsigned*)&lo;
    v.y = *(unsigned*)&hi;
    g_x1[n * HW + idx] = v;
}

// ---------------------------------------------------------------------------
// Stage 2: rotation sampling, smem-tiled.
// Block = one 32x32 output tile of one output image m. Stages the 48x48
// inverse-rotated input footprint into smem (coalesced), then all bilinear
// gathers are LDS. Thread = 4 horizontally-consecutive pixels -> 3 STG.128.
// ---------------------------------------------------------------------------
__global__ void __launch_bounds__(TPB) stage2_rotate(float* __restrict__ out)
{
    __shared__ uint2 tile[IN_DIM * PITCH];

    int m = blockIdx.y;                        // 0..419
    int r = m / (SS * BB);
    int n = m - r * (SS * BB);
    int tbx = blockIdx.x % (WW / TILE);
    int tby = blockIdx.x / (WW / TILE);
    int tx = tbx * TILE;                       // tile origin (output coords)
    int ty = tby * TILE;

    const float cx = 111.5f;
    float cs = c_cos[r], sn = c_sin[r];

    // Input bounding box of this tile (evaluate inverse map at 4 corners).
    float u0 = (float)tx - cx,        u1 = (float)(tx + TILE - 1) - cx;
    float v0 = (float)ty - cx,        v1 = (float)(ty + TILE - 1) - cx;
    float ix00 = u0*cs + v0*sn, ix01 = u0*cs + v1*sn;
    float ix10 = u1*cs + v0*sn, ix11 = u1*cs + v1*sn;
    float iy00 = -u0*sn + v0*cs, iy01 = -u0*sn + v1*cs;
    float iy10 = -u1*sn + v0*cs, iy11 = -u1*sn + v1*cs;
    int x_base = (int)floorf(fminf(fminf(ix00, ix01), fminf(ix10, ix11)) + cx) - 1;
    int y_base = (int)floorf(fminf(fminf(iy00, iy01), fminf(iy10, iy11)) + cx) - 1;

    // Stage the input tile (zero-fill out-of-image cells; their bilinear
    // weights are masked to zero below, value is irrelevant but must be safe).
    const uint2* __restrict__ img = g_x1 + n * HW;
    int tid = threadIdx.x;
    #pragma unroll
    for (int k = 0; k < (IN_DIM * IN_DIM) / TPB; k++) {
        int c = tid + k * TPB;
        int row = c / IN_DIM;
        int col = c - row * IN_DIM;
        int gy = y_base + row;
        int gx = x_base + col;
        uint2 val = make_uint2(0u, 0u);
        if ((unsigned)gy < HH && (unsigned)gx < WW)
            val = __ldg(img + gy * WW + gx);
        tile[row * PITCH + col] = val;
    }
    __syncthreads();

    // Compute: thread -> (quad qx, row y) within the tile.
    int qx = tid & 7;
    int yy = tid >> 3;                         // 0..31
    int w = tx + qx * 4;
    int h = ty + yy;

    float u = (float)w - cx;
    float v = (float)h - cx;
    float ix0 =  u * cs + v * sn + cx;
    float iy0 = -u * sn + v * cs + cx;

    float res[12];
    #pragma unroll
    for (int p = 0; p < 4; p++) {
        float jx = ix0 + (float)p * cs;
        float jy = iy0 - (float)p * sn;
        float x0f = floorf(jx), y0f = floorf(jy);
        int   x0  = (int)x0f,   y0  = (int)y0f;
        float fx = jx - x0f, fy = jy - y0f;

        float wx0 = (1.f - fx) * (((unsigned)x0       < WW) ? 1.f : 0.f);
        float wx1 =         fx * (((unsigned)(x0 + 1) < WW) ? 1.f : 0.f);
        float wy0 = (1.f - fy) * (((unsigned)y0       < HH) ? 1.f : 0.f);
        float wy1 =         fy * (((unsigned)(y0 + 1) < HH) ? 1.f : 0.f);

        int lx = x0 - x_base;                  // always within [0, IN_DIM-2]
        int ly = y0 - y_base;
        const uint2* row0 = tile + ly * PITCH + lx;
        uint2 r00 = row0[0];
        uint2 r01 = row0[1];
        uint2 r10 = row0[PITCH];
        uint2 r11 = row0[PITCH + 1];

        float w00 = wy0 * wx0, w01 = wy0 * wx1;
        float w10 = wy1 * wx0, w11 = wy1 * wx1;

        float2 a00 = __half22float2(*(__half2*)&r00.x);
        float2 b00 = __half22float2(*(__half2*)&r00.y);
        float2 a01 = __half22float2(*(__half2*)&r01.x);
        float2 b01 = __half22float2(*(__half2*)&r01.y);
        float2 a10 = __half22float2(*(__half2*)&r10.x);
        float2 b10 = __half22float2(*(__half2*)&r10.y);
        float2 a11 = __half22float2(*(__half2*)&r11.x);
        float2 b11 = __half22float2(*(__half2*)&r11.y);

        res[p*3 + 0] = w00*a00.x + w01*a01.x + w10*a10.x + w11*a11.x;
        res[p*3 + 1] = w00*a00.y + w01*a01.y + w10*a10.y + w11*a11.y;
        res[p*3 + 2] = w00*b00.x + w01*b01.x + w10*b10.x + w11*b11.x;
    }

    // 12 consecutive floats, 48B-aligned (w % 4 == 0).
    float4* o = (float4*)(out + ((size_t)m * HW + (size_t)h * WW + w) * 3);
    o[0] = make_float4(res[0], res[1], res[2],  res[3]);
    o[1] = make_float4(res[4], res[5], res[6],  res[7]);
    o[2] = make_float4(res[8], res[9], res[10], res[11]);
}

extern "C" void kernel_launch(void* const* d_in, const int* in_sizes, int n_in,
                              void* d_out, int out_size)
{
    (void)in_sizes; (void)n_in; (void)out_size;
    const float* xs = (const float*)d_in[0];
    float* out = (float*)d_out;

    dim3 blk(256);
    dim3 g1((HW + 255) / 256, SS * BB);                     // (196, 84)
    dim3 g2((WW / TILE) * (HH / TILE), RR * SS * BB);       // (49, 420)

    stage1_shift<<<g1, blk>>>(xs);
    stage2_rotate<<<g2, blk>>>(out);
}